// round 9
// baseline (speedup 1.0000x reference)
#include <cuda_runtime.h>
#include <cmath>
#include <complex>

// ============================================================================
// Selfmix: SO(3) self tensor product, LMAX=2, B x 1152 -> B x 3200 (fp32).
// R8: 4 channels per thread (LDG.128/STG.128, minimal LSU ops per byte)
// combined with packed f32x2 arithmetic (minimal issue per byte).
// ============================================================================

using u64 = unsigned long long;

// ---------------- packed f32x2 primitives (PTX-only on sm_103a) -------------
__device__ __forceinline__ u64 fma2(u64 a, u64 b, u64 c) {
  u64 d;
  asm("fma.rn.f32x2 %0, %1, %2, %3;" : "=l"(d) : "l"(a), "l"(b), "l"(c));
  return d;
}
__device__ __forceinline__ u64 mul2(u64 a, u64 b) {
  u64 d;
  asm("mul.rn.f32x2 %0, %1, %2;" : "=l"(d) : "l"(a), "l"(b));
  return d;
}
__device__ __forceinline__ u64 add2(u64 a, u64 b) {
  u64 d;
  asm("add.rn.f32x2 %0, %1, %2;" : "=l"(d) : "l"(a), "l"(b));
  return d;
}
__device__ __forceinline__ u64 pack2(float lo, float hi) {
  u64 d;
  asm("mov.b64 %0, {%1, %2};" : "=l"(d) : "f"(lo), "f"(hi));
  return d;
}

// two packed lanes = 4 fp32 channels
struct V4 { u64 a, b; };
__device__ __forceinline__ V4 fma4(u64 w, V4 p, V4 c) {
  return {fma2(w, p.a, c.a), fma2(w, p.b, c.b)};
}
__device__ __forceinline__ V4 mul4s(V4 x, u64 w) {  // packed scalar-per-lane
  return {mul2(x.a, w), mul2(x.b, w)};
}
__device__ __forceinline__ V4 mul4(V4 x, V4 y) {
  return {mul2(x.a, y.a), mul2(x.b, y.b)};
}
__device__ __forceinline__ V4 fma4v(V4 x, V4 y, V4 c) {
  return {fma2(x.a, y.a, c.a), fma2(x.b, y.b, c.b)};
}
__device__ __forceinline__ V4 add4(V4 x, V4 y) {
  return {add2(x.a, y.a), add2(x.b, y.b)};
}

// ---------------- compile-time structural nonzero mask ----------------------
__host__ __device__ constexpr bool structural(int l1, int l2, int lo,
                                              int a, int b, int c) {
  const int ma = a - l1, mb = b - l2, mc = c - lo;
  const int x = ma < 0 ? -ma : ma;
  const int y = mb < 0 ? -mb : mb;
  const int z = mc < 0 ? -mc : mc;
  const bool abs_ok = (z == x + y) || (z == (x > y ? x - y : y - x));
  const int nsin = (ma < 0 ? 1 : 0) + (mb < 0 ? 1 : 0) + (mc < 0 ? 1 : 0);
  const bool par_ok = ((nsin & 1) == ((l1 + l2 + lo) & 1));
  return abs_ok && par_ok;
}

// ---------------- by-value parameter block (constant bank) ------------------
// Each CG coefficient duplicated: float2{w, w} -> one 64-bit packed operand.
struct Params {
  float2 c000[1][1][1];
  float2 c110[3][3][1];
  float2 c220[5][5][1];
  float2 c011[1][3][3];
  float2 c121[3][5][3];
  float2 c022[1][5][5];
  float2 c112[3][3][5];
  float2 c122[3][5][5];
  float2 c222[5][5][5];
  float2 c123[3][5][7];
  float2 c224[5][5][9];
};  // 689 float2 = 5512 bytes

// ---------------- per-combo contraction, fully unrolled, packed x4 ----------
template <int L1, int L2, int LO>
__device__ __forceinline__ void combo(
    const float2 (&cg)[2 * L1 + 1][2 * L2 + 1][2 * LO + 1],
    const V4 (&xa)[2 * L1 + 1],
    const V4 (&xb)[2 * L2 + 1],
    V4 (&out)[2 * LO + 1],
    V4 s) {
  V4 ya[2 * L1 + 1];
#pragma unroll
  for (int a = 0; a < 2 * L1 + 1; a++) ya[a] = mul4(xa[a], s);
#pragma unroll
  for (int a = 0; a < 2 * L1 + 1; a++) {
#pragma unroll
    for (int b = 0; b < 2 * L2 + 1; b++) {
      bool any = false;
#pragma unroll
      for (int c = 0; c < 2 * LO + 1; c++) any = any || structural(L1, L2, LO, a, b, c);
      if (any) {  // compile-time constant after unroll
        const V4 p = mul4(ya[a], xb[b]);
#pragma unroll
        for (int c = 0; c < 2 * LO + 1; c++) {
          if (structural(L1, L2, LO, a, b, c)) {
            const u64 w = *reinterpret_cast<const u64*>(&cg[a][b][c]);
            out[c] = fma4(w, p, out[c]);
          }
        }
      }
    }
  }
}

__device__ __forceinline__ V4 ld4(const longlong2* ptr) {
  longlong2 v = *ptr;
  return {(u64)v.x, (u64)v.y};
}
__device__ __forceinline__ void st4(longlong2* ptr, V4 v) {
  longlong2 w;
  w.x = (long long)v.a;
  w.y = (long long)v.b;
  *ptr = w;
}

// ---------------- kernel: one thread = one (b, channel-quad) ----------------
__global__ __launch_bounds__(128) void selfmix_kernel(
    const longlong2* __restrict__ x, const longlong2* __restrict__ keep,
    const longlong2* __restrict__ mix, longlong2* __restrict__ out,
    int nthreads, const __grid_constant__ Params p) {
  const int t = blockIdx.x * 128 + threadIdx.x;
  if (t >= nthreads) return;
  const int b = t >> 5;       // batch row
  const int cq = t & 31;      // channel quad (channels 4cq..4cq+3)

  // ---- load inputs (128-bit, fully coalesced: 512B per warp-row) ----
  const longlong2* xr = x + (size_t)b * 288;
  V4 X0[1], X1[3], X2[5];
  X0[0] = ld4(xr + cq);
#pragma unroll
  for (int m = 0; m < 3; m++) X1[m] = ld4(xr + 32 + m * 32 + cq);
#pragma unroll
  for (int m = 0; m < 5; m++) X2[m] = ld4(xr + 128 + m * 32 + cq);

  const u64 HALF = pack2(0.5f, 0.5f);
  longlong2* orow = out + (size_t)b * 800;

  // ---- lo = 4 : (2,2->4) ----
  {
    const V4 s224 = mul4s(ld4(mix + 18 * 32 + cq), HALF);
    V4 O[9] = {};
    combo<2, 2, 4>(p.c224, X2, X2, O, s224);
#pragma unroll
    for (int k = 0; k < 9; k++) st4(orow + 512 + k * 32 + cq, O[k]);
  }
  // ---- lo = 3 : (1,2->3)+(2,1->3) merged (sigma=+1) ----
  {
    const V4 s123 = mul4s(add4(ld4(mix + 15 * 32 + cq), ld4(mix + 16 * 32 + cq)), HALF);
    V4 O[7] = {};
    combo<1, 2, 3>(p.c123, X1, X2, O, s123);
#pragma unroll
    for (int k = 0; k < 7; k++) st4(orow + 288 + k * 32 + cq, O[k]);
  }
  // ---- lo = 2 : (0,2)+(2,0), (1,1), (1,2)-(2,1), (2,2) + keep ----
  {
    const u64 NHALF = pack2(-0.5f, -0.5f);
    const V4 s022 = mul4s(add4(ld4(mix + 9 * 32 + cq), ld4(mix + 12 * 32 + cq)), HALF);
    const V4 s112 = mul4s(ld4(mix + 10 * 32 + cq), HALF);
    const V4 m11 = ld4(mix + 11 * 32 + cq), m13 = ld4(mix + 13 * 32 + cq);
    const V4 s122 = {fma2(m13.a, NHALF, mul2(m11.a, HALF)),
                     fma2(m13.b, NHALF, mul2(m11.b, HALF))};
    const V4 s222 = mul4s(ld4(mix + 14 * 32 + cq), HALF);
    const V4 k2 = ld4(keep + 64 + cq);
    V4 O[5] = {};
    combo<0, 2, 2>(p.c022, X0, X2, O, s022);
    combo<1, 1, 2>(p.c112, X1, X1, O, s112);
    combo<1, 2, 2>(p.c122, X1, X2, O, s122);
    combo<2, 2, 2>(p.c222, X2, X2, O, s222);
#pragma unroll
    for (int k = 0; k < 5; k++) {
      O[k] = fma4v(X2[k], k2, O[k]);
      st4(orow + 128 + k * 32 + cq, O[k]);
    }
  }
  // ---- lo = 1 : (0,1)+(1,0), (1,2)+(2,1) + keep ----
  {
    const V4 s011 = mul4s(add4(ld4(mix + 3 * 32 + cq), ld4(mix + 4 * 32 + cq)), HALF);
    const V4 s121 = mul4s(add4(ld4(mix + 6 * 32 + cq), ld4(mix + 7 * 32 + cq)), HALF);
    const V4 k1 = ld4(keep + 32 + cq);
    V4 O[3] = {};
    combo<0, 1, 1>(p.c011, X0, X1, O, s011);
    combo<1, 2, 1>(p.c121, X1, X2, O, s121);
#pragma unroll
    for (int k = 0; k < 3; k++) {
      O[k] = fma4v(X1[k], k1, O[k]);
      st4(orow + 32 + k * 32 + cq, O[k]);
    }
  }
  // ---- lo = 0 : (0,0), (1,1), (2,2) + keep ----
  {
    const V4 s000 = mul4s(ld4(mix + 0 * 32 + cq), HALF);
    const V4 s110 = mul4s(ld4(mix + 1 * 32 + cq), HALF);
    const V4 s220 = mul4s(ld4(mix + 2 * 32 + cq), HALF);
    const V4 k0 = ld4(keep + cq);
    V4 O[1] = {};
    combo<0, 0, 0>(p.c000, X0, X0, O, s000);
    combo<1, 1, 0>(p.c110, X1, X1, O, s110);
    combo<2, 2, 0>(p.c220, X2, X2, O, s220);
    O[0] = fma4v(X0[0], k0, O[0]);
    st4(orow + cq, O[0]);
  }
}

// ============================================================================
// Host: exact port of the reference CG construction (Racah + real basis).
// ============================================================================
static double factd(int n) {
  double r = 1.0;
  for (int i = 2; i <= n; i++) r *= (double)i;
  return r;
}

static void cg_complex_h(int l1, int l2, int l3, double C[5][5][9]) {
  for (int i = 0; i < 5; i++)
    for (int j = 0; j < 5; j++)
      for (int k = 0; k < 9; k++) C[i][j][k] = 0.0;
  for (int m1 = -l1; m1 <= l1; m1++) {
    for (int m2 = -l2; m2 <= l2; m2++) {
      const int m3 = m1 + m2;
      if (m3 < -l3 || m3 > l3) continue;
      double pre = std::sqrt((2 * l3 + 1) * factd(l1 + l2 - l3) * factd(l1 - l2 + l3) *
                             factd(-l1 + l2 + l3) / factd(l1 + l2 + l3 + 1));
      pre *= std::sqrt(factd(l3 + m3) * factd(l3 - m3) * factd(l1 - m1) *
                       factd(l1 + m1) * factd(l2 - m2) * factd(l2 + m2));
      double s = 0.0;
      for (int k = 0; k <= l1 + l2 - l3; k++) {
        const int den[6] = {k, l1 + l2 - l3 - k, l1 - m1 - k, l2 + m2 - k,
                            l3 - l2 + m1 + k, l3 - l1 - m2 + k};
        int mn = den[0];
        for (int t = 1; t < 6; t++) mn = den[t] < mn ? den[t] : mn;
        if (mn < 0) continue;
        double d = 1.0;
        for (int t = 0; t < 6; t++) d *= factd(den[t]);
        s += ((k & 1) ? -1.0 : 1.0) / d;
      }
      C[m1 + l1][m2 + l2][m3 + l3] = pre * s;
    }
  }
}

static void build_u(int l, std::complex<double> U[9][9]) {
  for (int i = 0; i < 9; i++)
    for (int j = 0; j < 9; j++) U[i][j] = 0.0;
  U[l][l] = 1.0;
  const double is2 = 1.0 / std::sqrt(2.0);
  for (int m = 1; m <= l; m++) {
    const double sgn = (m & 1) ? -1.0 : 1.0;
    U[l + m][l + m] = sgn * is2;
    U[l + m][l - m] = is2;
    U[l - m][l - m] = std::complex<double>(0.0, is2);
    U[l - m][l + m] = std::complex<double>(0.0, -sgn * is2);
  }
}

static void cg_real_h(int l1, int l2, int l3, float2* R) {
  const int d1 = 2 * l1 + 1, d2 = 2 * l2 + 1, d3 = 2 * l3 + 1;
  double C[5][5][9];
  cg_complex_h(l1, l2, l3, C);
  std::complex<double> U1[9][9], U2[9][9], U3[9][9];
  build_u(l1, U1);
  build_u(l2, U2);
  build_u(l3, U3);
  double Rre[5][5][9], Rim[5][5][9];
  double mxre = 0.0, mxim = 0.0;
  for (int a = 0; a < d1; a++) {
    for (int b = 0; b < d2; b++) {
      for (int c = 0; c < d3; c++) {
        std::complex<double> acc(0.0, 0.0);
        for (int i = 0; i < d1; i++)
          for (int j = 0; j < d2; j++)
            for (int k = 0; k < d3; k++) {
              if (C[i][j][k] == 0.0) continue;
              acc += U1[a][i] * U2[b][j] * std::conj(U3[c][k]) * C[i][j][k];
            }
        Rre[a][b][c] = acc.real();
        Rim[a][b][c] = acc.imag();
        if (std::fabs(acc.real()) > mxre) mxre = std::fabs(acc.real());
        if (std::fabs(acc.imag()) > mxim) mxim = std::fabs(acc.imag());
      }
    }
  }
  const bool use_im = mxim > mxre;
  for (int a = 0; a < d1; a++)
    for (int b = 0; b < d2; b++)
      for (int c = 0; c < d3; c++) {
        const float w = (float)(use_im ? Rim[a][b][c] : Rre[a][b][c]);
        R[(a * d2 + b) * d3 + c] = make_float2(w, w);  // duplicate for f32x2
      }
}

static void build_params(Params& p) {
  cg_real_h(0, 0, 0, &p.c000[0][0][0]);
  cg_real_h(1, 1, 0, &p.c110[0][0][0]);
  cg_real_h(2, 2, 0, &p.c220[0][0][0]);
  cg_real_h(0, 1, 1, &p.c011[0][0][0]);
  cg_real_h(1, 2, 1, &p.c121[0][0][0]);
  cg_real_h(0, 2, 2, &p.c022[0][0][0]);
  cg_real_h(1, 1, 2, &p.c112[0][0][0]);
  cg_real_h(1, 2, 2, &p.c122[0][0][0]);
  cg_real_h(2, 2, 2, &p.c222[0][0][0]);
  cg_real_h(1, 2, 3, &p.c123[0][0][0]);
  cg_real_h(2, 2, 4, &p.c224[0][0][0]);
}

// ============================================================================
extern "C" void kernel_launch(void* const* d_in, const int* in_sizes, int n_in,
                              void* d_out, int out_size) {
  (void)n_in;
  (void)out_size;
  const longlong2* x = (const longlong2*)d_in[0];     // (B,1152) fp32 = 288 l2/row
  const longlong2* keep = (const longlong2*)d_in[1];  // (384,)
  const longlong2* mix = (const longlong2*)d_in[2];   // (2432,)
  longlong2* out = (longlong2*)d_out;                 // (B,3200) fp32 = 800 l2/row

  const int B = in_sizes[0] / 1152;
  Params p;
  build_params(p);

  const int nthreads = B * 32;              // 4 channels per thread
  const int block = 128;
  const int grid = (nthreads + block - 1) / block;
  selfmix_kernel<<<grid, block>>>(x, keep, mix, out, nthreads, p);
}

// round 10
// speedup vs baseline: 1.0464x; 1.0464x over previous
#include <cuda_runtime.h>
#include <cmath>
#include <complex>

// ============================================================================
// Selfmix: SO(3) self tensor product, LMAX=2, B x 1152 -> B x 3200 (fp32).
// R9 = R7 (f32x2 body, per-section scales) + write-through stores (__stwt):
// bypass L2 dirty-writeback laziness so the DRAM write stream is smooth.
// ============================================================================

using u64 = unsigned long long;

// ---------------- packed f32x2 primitives (PTX-only on sm_103a) -------------
__device__ __forceinline__ u64 fma2(u64 a, u64 b, u64 c) {
  u64 d;
  asm("fma.rn.f32x2 %0, %1, %2, %3;" : "=l"(d) : "l"(a), "l"(b), "l"(c));
  return d;
}
__device__ __forceinline__ u64 mul2(u64 a, u64 b) {
  u64 d;
  asm("mul.rn.f32x2 %0, %1, %2;" : "=l"(d) : "l"(a), "l"(b));
  return d;
}
__device__ __forceinline__ u64 add2(u64 a, u64 b) {
  u64 d;
  asm("add.rn.f32x2 %0, %1, %2;" : "=l"(d) : "l"(a), "l"(b));
  return d;
}
__device__ __forceinline__ u64 pack2(float lo, float hi) {
  u64 d;
  asm("mov.b64 %0, {%1, %2};" : "=l"(d) : "f"(lo), "f"(hi));
  return d;
}
// write-through 64-bit store
__device__ __forceinline__ void stwt64(u64* ptr, u64 v) {
  asm volatile("st.global.wt.b64 [%0], %1;" :: "l"(ptr), "l"(v) : "memory");
}

// ---------------- compile-time structural nonzero mask ----------------------
__host__ __device__ constexpr bool structural(int l1, int l2, int lo,
                                              int a, int b, int c) {
  const int ma = a - l1, mb = b - l2, mc = c - lo;
  const int x = ma < 0 ? -ma : ma;
  const int y = mb < 0 ? -mb : mb;
  const int z = mc < 0 ? -mc : mc;
  const bool abs_ok = (z == x + y) || (z == (x > y ? x - y : y - x));
  const int nsin = (ma < 0 ? 1 : 0) + (mb < 0 ? 1 : 0) + (mc < 0 ? 1 : 0);
  const bool par_ok = ((nsin & 1) == ((l1 + l2 + lo) & 1));
  return abs_ok && par_ok;
}

// ---------------- by-value parameter block (constant bank) ------------------
// Each CG coefficient duplicated: float2{w, w} -> one 64-bit packed operand.
struct Params {
  float2 c000[1][1][1];
  float2 c110[3][3][1];
  float2 c220[5][5][1];
  float2 c011[1][3][3];
  float2 c121[3][5][3];
  float2 c022[1][5][5];
  float2 c112[3][3][5];
  float2 c122[3][5][5];
  float2 c222[5][5][5];
  float2 c123[3][5][7];
  float2 c224[5][5][9];
};  // 689 float2 = 5512 bytes

// ---------------- per-combo contraction, fully unrolled, packed -------------
template <int L1, int L2, int LO>
__device__ __forceinline__ void combo(
    const float2 (&cg)[2 * L1 + 1][2 * L2 + 1][2 * LO + 1],
    const u64 (&xa)[2 * L1 + 1],
    const u64 (&xb)[2 * L2 + 1],
    u64 (&out)[2 * LO + 1],
    u64 s) {
  u64 ya[2 * L1 + 1];
#pragma unroll
  for (int a = 0; a < 2 * L1 + 1; a++) ya[a] = mul2(xa[a], s);
#pragma unroll
  for (int a = 0; a < 2 * L1 + 1; a++) {
#pragma unroll
    for (int b = 0; b < 2 * L2 + 1; b++) {
      bool any = false;
#pragma unroll
      for (int c = 0; c < 2 * LO + 1; c++) any = any || structural(L1, L2, LO, a, b, c);
      if (any) {  // compile-time constant after unroll
        const u64 p = mul2(ya[a], xb[b]);
#pragma unroll
        for (int c = 0; c < 2 * LO + 1; c++) {
          if (structural(L1, L2, LO, a, b, c)) {
            const u64 w = *reinterpret_cast<const u64*>(&cg[a][b][c]);
            out[c] = fma2(w, p, out[c]);
          }
        }
      }
    }
  }
}

// ---------------- kernel: one thread = one (b, channel-pair) ----------------
__global__ __launch_bounds__(128) void selfmix_kernel(
    const u64* __restrict__ x, const u64* __restrict__ keep,
    const u64* __restrict__ mix, u64* __restrict__ out,
    int nthreads, const __grid_constant__ Params p) {
  const int t = blockIdx.x * 128 + threadIdx.x;
  if (t >= nthreads) return;
  const int b = t >> 6;       // batch row
  const int cp = t & 63;      // channel pair (channels 2cp, 2cp+1)

  // ---- load inputs (64-bit packed, fully coalesced) ----
  const u64* xr = x + (size_t)b * 576;
  u64 X0[1], X1[3], X2[5];
  X0[0] = xr[cp];
#pragma unroll
  for (int m = 0; m < 3; m++) X1[m] = xr[64 + m * 64 + cp];
#pragma unroll
  for (int m = 0; m < 5; m++) X2[m] = xr[256 + m * 64 + cp];

  const u64 HALF = pack2(0.5f, 0.5f);
  const u64 NHALF = pack2(-0.5f, -0.5f);
  u64* orow = out + (size_t)b * 1600;

  // ---- lo = 4 : (2,2->4) ----
  {
    const u64 s224 = mul2(mix[18 * 64 + cp], HALF);
    u64 O[9] = {};
    combo<2, 2, 4>(p.c224, X2, X2, O, s224);
#pragma unroll
    for (int k = 0; k < 9; k++) stwt64(orow + 1024 + k * 64 + cp, O[k]);
  }
  // ---- lo = 3 : (1,2->3)+(2,1->3) merged (sigma=+1) ----
  {
    const u64 s123 = mul2(add2(mix[15 * 64 + cp], mix[16 * 64 + cp]), HALF);
    u64 O[7] = {};
    combo<1, 2, 3>(p.c123, X1, X2, O, s123);
#pragma unroll
    for (int k = 0; k < 7; k++) stwt64(orow + 576 + k * 64 + cp, O[k]);
  }
  // ---- lo = 2 : (0,2)+(2,0), (1,1), (1,2)-(2,1), (2,2) + keep ----
  {
    const u64 s022 = mul2(add2(mix[9 * 64 + cp], mix[12 * 64 + cp]), HALF);
    const u64 s112 = mul2(mix[10 * 64 + cp], HALF);
    const u64 s122 = fma2(mix[13 * 64 + cp], NHALF,
                          mul2(mix[11 * 64 + cp], HALF));
    const u64 s222 = mul2(mix[14 * 64 + cp], HALF);
    const u64 k2 = keep[128 + cp];
    u64 O[5] = {};
    combo<0, 2, 2>(p.c022, X0, X2, O, s022);
    combo<1, 1, 2>(p.c112, X1, X1, O, s112);
    combo<1, 2, 2>(p.c122, X1, X2, O, s122);
    combo<2, 2, 2>(p.c222, X2, X2, O, s222);
#pragma unroll
    for (int k = 0; k < 5; k++) {
      O[k] = fma2(X2[k], k2, O[k]);
      stwt64(orow + 256 + k * 64 + cp, O[k]);
    }
  }
  // ---- lo = 1 : (0,1)+(1,0), (1,2)+(2,1) + keep ----
  {
    const u64 s011 = mul2(add2(mix[3 * 64 + cp], mix[4 * 64 + cp]), HALF);
    const u64 s121 = mul2(add2(mix[6 * 64 + cp], mix[7 * 64 + cp]), HALF);
    const u64 k1 = keep[64 + cp];
    u64 O[3] = {};
    combo<0, 1, 1>(p.c011, X0, X1, O, s011);
    combo<1, 2, 1>(p.c121, X1, X2, O, s121);
#pragma unroll
    for (int k = 0; k < 3; k++) {
      O[k] = fma2(X1[k], k1, O[k]);
      stwt64(orow + 64 + k * 64 + cp, O[k]);
    }
  }
  // ---- lo = 0 : (0,0), (1,1), (2,2) + keep ----
  {
    const u64 s000 = mul2(mix[0 * 64 + cp], HALF);
    const u64 s110 = mul2(mix[1 * 64 + cp], HALF);
    const u64 s220 = mul2(mix[2 * 64 + cp], HALF);
    const u64 k0 = keep[cp];
    u64 O[1] = {};
    combo<0, 0, 0>(p.c000, X0, X0, O, s000);
    combo<1, 1, 0>(p.c110, X1, X1, O, s110);
    combo<2, 2, 0>(p.c220, X2, X2, O, s220);
    O[0] = fma2(X0[0], k0, O[0]);
    stwt64(orow + cp, O[0]);
  }
}

// ============================================================================
// Host: exact port of the reference CG construction (Racah + real basis).
// ============================================================================
static double factd(int n) {
  double r = 1.0;
  for (int i = 2; i <= n; i++) r *= (double)i;
  return r;
}

static void cg_complex_h(int l1, int l2, int l3, double C[5][5][9]) {
  for (int i = 0; i < 5; i++)
    for (int j = 0; j < 5; j++)
      for (int k = 0; k < 9; k++) C[i][j][k] = 0.0;
  for (int m1 = -l1; m1 <= l1; m1++) {
    for (int m2 = -l2; m2 <= l2; m2++) {
      const int m3 = m1 + m2;
      if (m3 < -l3 || m3 > l3) continue;
      double pre = std::sqrt((2 * l3 + 1) * factd(l1 + l2 - l3) * factd(l1 - l2 + l3) *
                             factd(-l1 + l2 + l3) / factd(l1 + l2 + l3 + 1));
      pre *= std::sqrt(factd(l3 + m3) * factd(l3 - m3) * factd(l1 - m1) *
                       factd(l1 + m1) * factd(l2 - m2) * factd(l2 + m2));
      double s = 0.0;
      for (int k = 0; k <= l1 + l2 - l3; k++) {
        const int den[6] = {k, l1 + l2 - l3 - k, l1 - m1 - k, l2 + m2 - k,
                            l3 - l2 + m1 + k, l3 - l1 - m2 + k};
        int mn = den[0];
        for (int t = 1; t < 6; t++) mn = den[t] < mn ? den[t] : mn;
        if (mn < 0) continue;
        double d = 1.0;
        for (int t = 0; t < 6; t++) d *= factd(den[t]);
        s += ((k & 1) ? -1.0 : 1.0) / d;
      }
      C[m1 + l1][m2 + l2][m3 + l3] = pre * s;
    }
  }
}

static void build_u(int l, std::complex<double> U[9][9]) {
  for (int i = 0; i < 9; i++)
    for (int j = 0; j < 9; j++) U[i][j] = 0.0;
  U[l][l] = 1.0;
  const double is2 = 1.0 / std::sqrt(2.0);
  for (int m = 1; m <= l; m++) {
    const double sgn = (m & 1) ? -1.0 : 1.0;
    U[l + m][l + m] = sgn * is2;
    U[l + m][l - m] = is2;
    U[l - m][l - m] = std::complex<double>(0.0, is2);
    U[l - m][l + m] = std::complex<double>(0.0, -sgn * is2);
  }
}

static void cg_real_h(int l1, int l2, int l3, float2* R) {
  const int d1 = 2 * l1 + 1, d2 = 2 * l2 + 1, d3 = 2 * l3 + 1;
  double C[5][5][9];
  cg_complex_h(l1, l2, l3, C);
  std::complex<double> U1[9][9], U2[9][9], U3[9][9];
  build_u(l1, U1);
  build_u(l2, U2);
  build_u(l3, U3);
  double Rre[5][5][9], Rim[5][5][9];
  double mxre = 0.0, mxim = 0.0;
  for (int a = 0; a < d1; a++) {
    for (int b = 0; b < d2; b++) {
      for (int c = 0; c < d3; c++) {
        std::complex<double> acc(0.0, 0.0);
        for (int i = 0; i < d1; i++)
          for (int j = 0; j < d2; j++)
            for (int k = 0; k < d3; k++) {
              if (C[i][j][k] == 0.0) continue;
              acc += U1[a][i] * U2[b][j] * std::conj(U3[c][k]) * C[i][j][k];
            }
        Rre[a][b][c] = acc.real();
        Rim[a][b][c] = acc.imag();
        if (std::fabs(acc.real()) > mxre) mxre = std::fabs(acc.real());
        if (std::fabs(acc.imag()) > mxim) mxim = std::fabs(acc.imag());
      }
    }
  }
  const bool use_im = mxim > mxre;
  for (int a = 0; a < d1; a++)
    for (int b = 0; b < d2; b++)
      for (int c = 0; c < d3; c++) {
        const float w = (float)(use_im ? Rim[a][b][c] : Rre[a][b][c]);
        R[(a * d2 + b) * d3 + c] = make_float2(w, w);  // duplicate for f32x2
      }
}

static void build_params(Params& p) {
  cg_real_h(0, 0, 0, &p.c000[0][0][0]);
  cg_real_h(1, 1, 0, &p.c110[0][0][0]);
  cg_real_h(2, 2, 0, &p.c220[0][0][0]);
  cg_real_h(0, 1, 1, &p.c011[0][0][0]);
  cg_real_h(1, 2, 1, &p.c121[0][0][0]);
  cg_real_h(0, 2, 2, &p.c022[0][0][0]);
  cg_real_h(1, 1, 2, &p.c112[0][0][0]);
  cg_real_h(1, 2, 2, &p.c122[0][0][0]);
  cg_real_h(2, 2, 2, &p.c222[0][0][0]);
  cg_real_h(1, 2, 3, &p.c123[0][0][0]);
  cg_real_h(2, 2, 4, &p.c224[0][0][0]);
}

// ============================================================================
extern "C" void kernel_launch(void* const* d_in, const int* in_sizes, int n_in,
                              void* d_out, int out_size) {
  (void)n_in;
  (void)out_size;
  const u64* x = (const u64*)d_in[0];       // (B, 1152) fp32 = 576 u64/row
  const u64* keep = (const u64*)d_in[1];    // (384,)
  const u64* mix = (const u64*)d_in[2];     // (2432,)
  u64* out = (u64*)d_out;                   // (B, 3200) fp32 = 1600 u64/row

  const int B = in_sizes[0] / 1152;
  Params p;
  build_params(p);

  const int nthreads = B * 64;              // 2 channels per thread (1 f32x2 lane)
  const int block = 128;
  const int grid = (nthreads + block - 1) / block;
  selfmix_kernel<<<grid, block>>>(x, keep, mix, out, nthreads, p);
}